// round 7
// baseline (speedup 1.0000x reference)
#include <cuda_runtime.h>
#include <cuda_bf16.h>
#include <cstdint>

// ---------------- problem constants ----------------
#define D      768
#define QTOT   512
#define NTOT   262144
#define KTOP   10

#define TM     256                 // queries per CTA
#define TN     128                 // lib rows per CTA
#define BK     128                 // k bytes (int8) per stage
#define NST    (D / BK)            // 6 stages
#define NTILES (NTOT / TN)         // 2048
#define KSEL   24                  // candidates rescored per query

#define SQ     21.0f               // int8 quant scale (covers +-6 sigma, no clip)

// ---------------- scratch ----------------
__device__ uint32_t g_qi8[(size_t)QTOT * D / 4];          // queries int8 (packed)
__device__ uint32_t g_li8[(size_t)NTOT * D / 4];          // lib int8 (packed) ~201MB
__device__ float    g_xsq[NTOT];                          // exact fp32 row norms
__device__ float4   g_cd4[(size_t)QTOT * NTILES];         // per-tile top-4 dist
__device__ int4     g_ci4[(size_t)QTOT * NTILES];         // per-tile top-4 idx

// ---------------- helpers ----------------
__device__ __forceinline__ uint32_t smem_u32(const void* p) {
    uint32_t a;
    asm("{ .reg .u64 t; cvta.to.shared.u64 t, %1; cvt.u32.u64 %0, t; }" : "=r"(a) : "l"(p));
    return a;
}
__device__ __forceinline__ uint32_t q4pack(float a, float b, float c, float d) {
    int ia = __float2int_rn(fminf(fmaxf(a * SQ, -127.f), 127.f));
    int ib = __float2int_rn(fminf(fmaxf(b * SQ, -127.f), 127.f));
    int ic = __float2int_rn(fminf(fmaxf(c * SQ, -127.f), 127.f));
    int id = __float2int_rn(fminf(fmaxf(d * SQ, -127.f), 127.f));
    return (uint32_t)(ia & 0xff) | ((uint32_t)(ib & 0xff) << 8) |
           ((uint32_t)(ic & 0xff) << 16) | ((uint32_t)(id & 0xff) << 24);
}
#define SWZ(x) ((x) ^ (((x) >> 3) & 0x70))

#define CPASYNC16(dst, src) \
    asm volatile("cp.async.cg.shared.global [%0], [%1], 16;" :: "r"(dst), "l"(src))
#define CPCOMMIT() asm volatile("cp.async.commit_group;" ::: "memory")
#define CPWAIT(n)  asm volatile("cp.async.wait_group %0;" :: "n"(n) : "memory")

__device__ __forceinline__ void ldm_x4(uint32_t* r, uint32_t addr) {
    asm volatile("ldmatrix.sync.aligned.m8n8.x4.shared.b16 {%0,%1,%2,%3}, [%4];"
                 : "=r"(r[0]), "=r"(r[1]), "=r"(r[2]), "=r"(r[3]) : "r"(addr));
}
__device__ __forceinline__ void imma_s8(int* c, const uint32_t* a, const uint32_t* b) {
    asm volatile("mma.sync.aligned.m16n8k32.row.col.s32.s8.s8.s32 "
                 "{%0,%1,%2,%3}, {%4,%5,%6,%7}, {%8,%9}, {%0,%1,%2,%3};"
                 : "+r"(c[0]), "+r"(c[1]), "+r"(c[2]), "+r"(c[3])
                 : "r"(a[0]), "r"(a[1]), "r"(a[2]), "r"(a[3]), "r"(b[0]), "r"(b[1]));
}

// ---------------- kernel 1a: query fp32 -> int8 ----------------
__global__ void qconv_kernel(const float* __restrict__ query) {
    int i = blockIdx.x * 256 + threadIdx.x;           // 98304 u32 granules
    float4 v = ((const float4*)query)[i];
    g_qi8[i] = q4pack(v.x, v.y, v.z, v.w);
}

// ---------------- kernel 1b: lib fp32 -> int8 + exact ||x||^2 ----------------
__global__ __launch_bounds__(256)
void libquant_kernel(const float* __restrict__ lib) {
    const int lane = threadIdx.x & 31;
    const int row  = blockIdx.x * 8 + (threadIdx.x >> 5);
    const float4* src = (const float4*)(lib + (size_t)row * D);
    float ssq = 0.f;
#pragma unroll
    for (int g = 0; g < 6; g++) {
        float4 v = src[g * 32 + lane];
        g_li8[(size_t)row * 192 + g * 32 + lane] = q4pack(v.x, v.y, v.z, v.w);
        ssq += v.x * v.x + v.y * v.y + v.z * v.z + v.w * v.w;
    }
#pragma unroll
    for (int o = 16; o; o >>= 1) ssq += __shfl_xor_sync(0xffffffffu, ssq, o);
    if (lane == 0) g_xsq[row] = ssq;
}

// ---------------- kernel 2: IMMA GEMM + per-tile approx top-4 ----------------
#define SA_OFF  0                       // 2 x 32768  (256 rows x 128B)
#define SB_OFF  65536                   // 2 x 16384  (128 rows x 128B)
#define XSQ_OFF 98304                   // 128 floats
#define SMEM_TOTAL (XSQ_OFF + 512)

__global__ __launch_bounds__(256, 1)
void dist_kernel() {
    extern __shared__ char smem[];
    const uint32_t sbase = smem_u32(smem);
    float* xsq_s = (float*)(smem + XSQ_OFF);

    const int tid  = threadIdx.x;
    const int lane = tid & 31;
    const int wid  = tid >> 5;           // 8 warps
    const int wm   = wid >> 1;           // 0..3 (64-row m block)
    const int wn   = wid & 1;            // 0..1 (64-col n block)
    const int qh   = blockIdx.x;         // query half (fast dim -> lib L2 reuse)
    const int bx   = blockIdx.y;         // lib tile
    const int n0   = bx * TN;
    const int m_base = wm * 64;
    const int n_base = wn * 64;

    if (tid < TN) xsq_s[tid] = g_xsq[n0 + tid];

    const char* Ag = (const char*)g_qi8 + (size_t)qh * TM * D;
    const char* Bg = (const char*)g_li8 + (size_t)n0 * D;

    // prologue: stage 0
#pragma unroll
    for (int j = 0; j < 8; j++) {
        int idx = j * 256 + tid;
        int r = idx >> 3, g = idx & 7;
        CPASYNC16(sbase + SA_OFF + SWZ(r * 128 + g * 16), Ag + (size_t)r * D + g * 16);
    }
#pragma unroll
    for (int j = 0; j < 4; j++) {
        int idx = j * 256 + tid;
        int r = idx >> 3, g = idx & 7;
        CPASYNC16(sbase + SB_OFF + SWZ(r * 128 + g * 16), Bg + (size_t)r * D + g * 16);
    }
    CPCOMMIT();

    int acc[4][8][4];
#pragma unroll
    for (int a = 0; a < 4; a++)
#pragma unroll
        for (int b = 0; b < 8; b++)
#pragma unroll
            for (int c = 0; c < 4; c++) acc[a][b][c] = 0;

    for (int kc = 0; kc < NST; kc++) {
        const int buf = kc & 1;
        if (kc + 1 < NST) {
            const int nb = (buf ^ 1);
            const int ko = (kc + 1) * BK;
#pragma unroll
            for (int j = 0; j < 8; j++) {
                int idx = j * 256 + tid;
                int r = idx >> 3, g = idx & 7;
                CPASYNC16(sbase + SA_OFF + nb * 32768 + SWZ(r * 128 + g * 16),
                          Ag + (size_t)r * D + ko + g * 16);
            }
#pragma unroll
            for (int j = 0; j < 4; j++) {
                int idx = j * 256 + tid;
                int r = idx >> 3, g = idx & 7;
                CPASYNC16(sbase + SB_OFF + nb * 16384 + SWZ(r * 128 + g * 16),
                          Bg + (size_t)r * D + ko + g * 16);
            }
            CPCOMMIT();
            CPWAIT(1);
        } else {
            CPWAIT(0);
        }
        __syncthreads();                   // stage kc resident

        const uint32_t aB = sbase + SA_OFF + buf * 32768;
        const uint32_t bB = sbase + SB_OFF + buf * 16384;
#pragma unroll
        for (int s = 0; s < 4; s++) {      // 4 x k32
            uint32_t afr[4][4], bfr[8][2];
#pragma unroll
            for (int mi = 0; mi < 4; mi++) {
                int row = m_base + mi * 16 + (lane & 15);
                int c16 = 2 * s + (lane >> 4);
                ldm_x4(afr[mi], aB + SWZ(row * 128 + c16 * 16));
            }
#pragma unroll
            for (int nb2 = 0; nb2 < 4; nb2++) {
                uint32_t t4[4];
                int row = n_base + nb2 * 16 + (lane & 7) + ((lane >> 4) << 3);
                int c16 = 2 * s + ((lane >> 3) & 1);
                ldm_x4(t4, bB + SWZ(row * 128 + c16 * 16));
                bfr[nb2 * 2][0] = t4[0]; bfr[nb2 * 2][1] = t4[1];
                bfr[nb2 * 2 + 1][0] = t4[2]; bfr[nb2 * 2 + 1][1] = t4[3];
            }
#pragma unroll
            for (int mi = 0; mi < 4; mi++)
#pragma unroll
                for (int ni = 0; ni < 8; ni++)
                    imma_s8(acc[mi][ni], afr[mi], bfr[ni]);
        }
        __syncthreads();                   // buffer reusable
    }

    // ---- epilogue: approx dist + per-(q,tile) top-4 ----
    const float NEG2RS = -2.0f / (SQ * SQ);
    float* slab  = (float*)(smem + SA_OFF);          // 64 x 128 floats
    float* candd = (float*)(smem + SB_OFF);          // 64 x 16
    int*   candi = (int*)(smem + SB_OFF + 4096);     // 64 x 16

    for (int ms = 0; ms < 4; ms++) {
        __syncthreads();
        if (wm == ms) {
#pragma unroll
            for (int mi = 0; mi < 4; mi++)
#pragma unroll
                for (int ni = 0; ni < 8; ni++)
#pragma unroll
                    for (int c = 0; c < 4; c++) {
                        int row = mi * 16 + (lane >> 2) + (c >> 1) * 8;
                        int col = n_base + ni * 8 + (lane & 3) * 2 + (c & 1);
                        slab[row * 128 + col] = (float)acc[mi][ni][c];   // exact: |acc|<2^24
                    }
        }
        __syncthreads();
        {
            int r = tid >> 2, seg = tid & 3;
            float t0, t1, t2, t3; int i0, i1, i2, i3;
            t0 = t1 = t2 = t3 = __int_as_float(0x7f800000);
            i0 = i1 = i2 = i3 = 0;
#pragma unroll
            for (int j = 0; j < 32; j++) {
                int col = seg * 32 + j;
                float dh = fmaf(NEG2RS, slab[r * 128 + col], xsq_s[col]);
                if (dh < t3) {
                    t3 = dh; i3 = n0 + col;
                    if (t3 < t2) { float a = t2; t2 = t3; t3 = a; int bw = i2; i2 = i3; i3 = bw;
                        if (t2 < t1) { a = t1; t1 = t2; t2 = a; bw = i1; i1 = i2; i2 = bw;
                            if (t1 < t0) { a = t0; t0 = t1; t1 = a; bw = i0; i0 = i1; i1 = bw; }
                        }
                    }
                }
            }
            int base = r * 16 + seg * 4;
            candd[base] = t0; candd[base + 1] = t1; candd[base + 2] = t2; candd[base + 3] = t3;
            candi[base] = i0; candi[base + 1] = i1; candi[base + 2] = i2; candi[base + 3] = i3;
        }
        __syncthreads();
        if (tid < 64) {
            float t0, t1, t2, t3; int i0, i1, i2, i3;
            t0 = t1 = t2 = t3 = __int_as_float(0x7f800000);
            i0 = i1 = i2 = i3 = 0x7fffffff;
#pragma unroll
            for (int t = 0; t < 16; t++) {
                float d = candd[tid * 16 + t]; int i = candi[tid * 16 + t];
                if (d < t3 || (d == t3 && i < i3)) {
                    t3 = d; i3 = i;
                    if (t3 < t2 || (t3 == t2 && i3 < i2)) { float a = t2; t2 = t3; t3 = a; int bw = i2; i2 = i3; i3 = bw;
                        if (t2 < t1 || (t2 == t1 && i2 < i1)) { a = t1; t1 = t2; t2 = a; bw = i1; i1 = i2; i2 = bw;
                            if (t1 < t0 || (t1 == t0 && i1 < i0)) { a = t0; t0 = t1; t1 = a; bw = i0; i0 = i1; i1 = bw; }
                        }
                    }
                }
            }
            int q = qh * TM + ms * 64 + tid;
            g_cd4[(size_t)q * NTILES + bx] = make_float4(t0, t1, t2, t3);
            g_ci4[(size_t)q * NTILES + bx] = make_int4(i0, i1, i2, i3);
        }
    }
}

// ---------------- kernel 3: merge approx candidates + exact rescore ----------------
__global__ __launch_bounds__(256)
void merge_kernel(const float* __restrict__ query, const float* __restrict__ lib,
                  float* __restrict__ out) {
    __shared__ float qrow[D];
    __shared__ float sd[1536];
    __shared__ int   si[1536];
    __shared__ float wred[8];
    __shared__ int   wredi[8];
    __shared__ int   sel[KSEL];
    __shared__ float ed[KSEL];
    __shared__ int   eidx[KSEL];
    __shared__ float s_qsq;

    const int q = blockIdx.x, tid = threadIdx.x, lane = tid & 31, w = tid >> 5;
    const float INF = __int_as_float(0x7f800000);

    for (int i = tid; i < D; i += 256) qrow[i] = query[(size_t)q * D + i];
    __syncthreads();
    {
        float s = 0.f;
        for (int i = tid; i < D; i += 256) s = fmaf(qrow[i], qrow[i], s);
#pragma unroll
        for (int o = 16; o; o >>= 1) s += __shfl_xor_sync(0xffffffffu, s, o);
        if (lane == 0) wred[w] = s;
        __syncthreads();
        if (tid == 0) { float t = 0.f; for (int i = 0; i < 8; i++) t += wred[i]; s_qsq = t; }
    }

    const float* cd = (const float*)g_cd4 + (size_t)q * NTILES * 4;
    const int*   ci = (const int*)g_ci4 + (size_t)q * NTILES * 4;
    float d6[6]; int x6[6];
#pragma unroll
    for (int j = 0; j < 6; j++) { d6[j] = INF; x6[j] = 0x7fffffff; }
    for (int j = 0; j < 32; j++) {
        int s2 = tid + j * 256;
        float dv = cd[s2]; int iv = ci[s2];
        if (dv < d6[5]) {
            d6[5] = dv; x6[5] = iv;
#pragma unroll
            for (int p = 5; p > 0; p--)
                if (d6[p] < d6[p - 1]) {
                    float a = d6[p]; d6[p] = d6[p - 1]; d6[p - 1] = a;
                    int bw = x6[p]; x6[p] = x6[p - 1]; x6[p - 1] = bw;
                }
        }
    }
#pragma unroll
    for (int j = 0; j < 6; j++) { sd[tid * 6 + j] = d6[j]; si[tid * 6 + j] = x6[j]; }
    __syncthreads();

    for (int it = 0; it < KSEL; it++) {
        float bd = INF; int bs = -1;
#pragma unroll
        for (int j = 0; j < 6; j++) {
            int s2 = tid * 6 + j;
            float v = sd[s2];
            if (v < bd) { bd = v; bs = s2; }
        }
#pragma unroll
        for (int o = 16; o; o >>= 1) {
            float od = __shfl_down_sync(0xffffffffu, bd, o);
            int   os = __shfl_down_sync(0xffffffffu, bs, o);
            if (od < bd) { bd = od; bs = os; }
        }
        if (lane == 0) { wred[w] = bd; wredi[w] = bs; }
        __syncthreads();
        if (tid == 0) {
            float m = INF; int ms = -1;
            for (int ww = 0; ww < 8; ww++) if (wred[ww] < m) { m = wred[ww]; ms = wredi[ww]; }
            sel[it] = si[ms];
            sd[ms] = INF;
        }
        __syncthreads();
    }

    for (int c = w; c < KSEL; c += 8) {
        int n = sel[c];
        const float* xr = lib + (size_t)n * D;
        float dot = 0.f, ssq = 0.f;
#pragma unroll
        for (int j = 0; j < D / 32; j++) {
            float xv = xr[lane + j * 32], qv = qrow[lane + j * 32];
            dot = fmaf(qv, xv, dot);
            ssq = fmaf(xv, xv, ssq);
        }
#pragma unroll
        for (int o = 16; o; o >>= 1) {
            dot += __shfl_xor_sync(0xffffffffu, dot, o);
            ssq += __shfl_xor_sync(0xffffffffu, ssq, o);
        }
        if (lane == 0) { ed[c] = s_qsq - 2.f * dot + ssq; eidx[c] = n; }
    }
    __syncthreads();

    if (tid == 0) {
        unsigned used = 0;
        for (int it = 0; it < KTOP; it++) {
            float bd = INF; int bi = 0x7fffffff, b = -1;
            for (int c = 0; c < KSEL; c++)
                if (!((used >> c) & 1u)) {
                    if (ed[c] < bd || (ed[c] == bd && eidx[c] < bi)) { bd = ed[c]; bi = eidx[c]; b = c; }
                }
            used |= 1u << b;
            out[q * KTOP + it]               = bd;
            out[QTOT * KTOP + q * KTOP + it] = (float)bi;
        }
    }
}

// ---------------- launcher ----------------
extern "C" void kernel_launch(void* const* d_in, const int* in_sizes, int n_in,
                              void* d_out, int out_size) {
    const float* query = (const float*)d_in[0];
    const float* lib   = (const float*)d_in[1];
    float* out = (float*)d_out;
    (void)n_in; (void)out_size; (void)in_sizes;

    cudaFuncSetAttribute(dist_kernel,
                         cudaFuncAttributeMaxDynamicSharedMemorySize, SMEM_TOTAL);

    qconv_kernel<<<QTOT * D / 4 / 256, 256>>>(query);
    libquant_kernel<<<NTOT / 8, 256>>>(lib);
    dim3 grid(QTOT / TM, NTILES);
    dist_kernel<<<grid, 256, SMEM_TOTAL>>>();
    merge_kernel<<<QTOT, 256>>>(query, lib, out);
}

// round 8
// speedup vs baseline: 1.7213x; 1.7213x over previous
#include <cuda_runtime.h>
#include <cuda_bf16.h>
#include <cstdint>

// ---------------- problem constants ----------------
#define D      768
#define QTOT   512
#define NTOT   262144
#define KTOP   10

#define TM     128                 // queries per CTA
#define TN     128                 // lib rows per CTA
#define BK     64                  // k per stage (bf16) = 128B rows
#define NST    (D / BK)            // 12 stages
#define NTILES (NTOT / TN)         // 2048
#define KSEL   24                  // candidates rescored per query

// ---------------- scratch ----------------
__device__ uint4  g_qbf[(size_t)QTOT * D / 8];            // queries bf16
__device__ uint2  g_lbf[(size_t)NTOT * D / 4];            // lib bf16 (384MB)
__device__ float  g_xsq[NTOT];                            // exact fp32 row norms
__device__ float4 g_cd4[(size_t)QTOT * NTILES];           // per-tile top-4 dist
__device__ int4   g_ci4[(size_t)QTOT * NTILES];           // per-tile top-4 idx

// ---------------- helpers ----------------
__device__ __forceinline__ uint32_t smem_u32(const void* p) {
    uint32_t a;
    asm("{ .reg .u64 t; cvta.to.shared.u64 t, %1; cvt.u32.u64 %0, t; }" : "=r"(a) : "l"(p));
    return a;
}
__device__ __forceinline__ unsigned pk_bf2(float a, float b) {
    __nv_bfloat162 t = __floats2bfloat162_rn(a, b);
    return *reinterpret_cast<unsigned*>(&t);
}
#define SWZ(x) ((x) ^ (((x) >> 3) & 0x70))

#define CPASYNC16(dst, src) \
    asm volatile("cp.async.cg.shared.global [%0], [%1], 16;" :: "r"(dst), "l"(src))
#define CPCOMMIT() asm volatile("cp.async.commit_group;" ::: "memory")
#define CPWAIT(n)  asm volatile("cp.async.wait_group %0;" :: "n"(n) : "memory")

__device__ __forceinline__ void ldm_x4(uint32_t* r, uint32_t addr) {
    asm volatile("ldmatrix.sync.aligned.m8n8.x4.shared.b16 {%0,%1,%2,%3}, [%4];"
                 : "=r"(r[0]), "=r"(r[1]), "=r"(r[2]), "=r"(r[3]) : "r"(addr));
}
__device__ __forceinline__ void mma_bf16(float* c, const uint32_t* a, const uint32_t* b) {
    asm volatile("mma.sync.aligned.m16n8k16.row.col.f32.bf16.bf16.f32 "
                 "{%0,%1,%2,%3}, {%4,%5,%6,%7}, {%8,%9}, {%0,%1,%2,%3};"
                 : "+f"(c[0]), "+f"(c[1]), "+f"(c[2]), "+f"(c[3])
                 : "r"(a[0]), "r"(a[1]), "r"(a[2]), "r"(a[3]), "r"(b[0]), "r"(b[1]));
}

// ---------------- kernel 1a: query fp32 -> bf16 ----------------
__global__ void qconv_kernel(const float* __restrict__ query) {
    int i = blockIdx.x * 256 + threadIdx.x;
    const float4* src = (const float4*)query;
    float4 a = src[2 * i], b = src[2 * i + 1];
    uint4 o;
    o.x = pk_bf2(a.x, a.y); o.y = pk_bf2(a.z, a.w);
    o.z = pk_bf2(b.x, b.y); o.w = pk_bf2(b.z, b.w);
    g_qbf[i] = o;
}

// ---------------- kernel 1b: lib fp32 -> bf16 + exact ||x||^2 ----------------
__global__ __launch_bounds__(256)
void libconv_kernel(const float* __restrict__ lib) {
    const int lane = threadIdx.x & 31;
    const int row  = blockIdx.x * 8 + (threadIdx.x >> 5);
    const float4* src = (const float4*)(lib + (size_t)row * D);
    float ssq = 0.f;
#pragma unroll
    for (int g = 0; g < 6; g++) {
        float4 v = src[g * 32 + lane];
        uint2 o;
        o.x = pk_bf2(v.x, v.y); o.y = pk_bf2(v.z, v.w);
        g_lbf[(size_t)row * 192 + g * 32 + lane] = o;
        ssq += v.x * v.x + v.y * v.y + v.z * v.z + v.w * v.w;
    }
#pragma unroll
    for (int o = 16; o; o >>= 1) ssq += __shfl_xor_sync(0xffffffffu, ssq, o);
    if (lane == 0) g_xsq[row] = ssq;
}

// ---------------- kernel 2: HMMA GEMM + per-tile approx top-4 ----------------
#define SA_OFF  0                       // 2 x 16384 (128 rows x 128B)
#define SB_OFF  32768                   // 2 x 16384
#define XSQ_OFF 65536                   // 128 floats
#define SMEM_TOTAL (XSQ_OFF + 512)

__global__ __launch_bounds__(256, 2)
void dist_kernel() {
    extern __shared__ char smem[];
    const uint32_t sbase = smem_u32(smem);
    float* xsq_s = (float*)(smem + XSQ_OFF);

    const int tid  = threadIdx.x;
    const int lane = tid & 31;
    const int wid  = tid >> 5;           // 8 warps
    const int wm   = wid >> 1;           // 0..3 (32-row m block)
    const int wn   = wid & 1;            // 0..1 (64-col n block)
    const int qh   = blockIdx.x;         // query block (fast dim -> lib L2 reuse)
    const int bx   = blockIdx.y;         // lib tile
    const int n0   = bx * TN;
    const int m_base = wm * 32;
    const int n_base = wn * 64;

    if (tid < TN) xsq_s[tid] = g_xsq[n0 + tid];

    const char* Ag = (const char*)g_qbf + (size_t)qh * TM * D * 2;
    const char* Bg = (const char*)g_lbf + (size_t)n0 * D * 2;

    // prologue: stage 0 (A: 1024 granules/256thr = 4 ea; B same)
#pragma unroll
    for (int j = 0; j < 4; j++) {
        int idx = j * 256 + tid;
        int r = idx >> 3, g = idx & 7;
        CPASYNC16(sbase + SA_OFF + SWZ(r * 128 + g * 16), Ag + (size_t)r * 1536 + g * 16);
    }
#pragma unroll
    for (int j = 0; j < 4; j++) {
        int idx = j * 256 + tid;
        int r = idx >> 3, g = idx & 7;
        CPASYNC16(sbase + SB_OFF + SWZ(r * 128 + g * 16), Bg + (size_t)r * 1536 + g * 16);
    }
    CPCOMMIT();

    float acc[2][8][4];
#pragma unroll
    for (int a = 0; a < 2; a++)
#pragma unroll
        for (int b = 0; b < 8; b++)
#pragma unroll
            for (int c = 0; c < 4; c++) acc[a][b][c] = 0.f;

    for (int kc = 0; kc < NST; kc++) {
        const int buf = kc & 1;
        if (kc + 1 < NST) {
            const int nb = buf ^ 1;
            const int ko = (kc + 1) * 128;       // byte offset within row
#pragma unroll
            for (int j = 0; j < 4; j++) {
                int idx = j * 256 + tid;
                int r = idx >> 3, g = idx & 7;
                CPASYNC16(sbase + SA_OFF + nb * 16384 + SWZ(r * 128 + g * 16),
                          Ag + (size_t)r * 1536 + ko + g * 16);
            }
#pragma unroll
            for (int j = 0; j < 4; j++) {
                int idx = j * 256 + tid;
                int r = idx >> 3, g = idx & 7;
                CPASYNC16(sbase + SB_OFF + nb * 16384 + SWZ(r * 128 + g * 16),
                          Bg + (size_t)r * 1536 + ko + g * 16);
            }
            CPCOMMIT();
            CPWAIT(1);
        } else {
            CPWAIT(0);
        }
        __syncthreads();                   // stage kc resident

        const uint32_t aB = sbase + SA_OFF + buf * 16384;
        const uint32_t bB = sbase + SB_OFF + buf * 16384;
#pragma unroll
        for (int s = 0; s < 4; s++) {      // 4 x k16
            uint32_t afr[2][4], bfr[8][2];
#pragma unroll
            for (int mi = 0; mi < 2; mi++) {
                int row = m_base + mi * 16 + (lane & 15);
                int c16 = 2 * s + (lane >> 4);
                ldm_x4(afr[mi], aB + SWZ(row * 128 + c16 * 16));
            }
#pragma unroll
            for (int nb2 = 0; nb2 < 4; nb2++) {
                uint32_t t4[4];
                int row = n_base + nb2 * 16 + (lane & 7) + ((lane >> 4) << 3);
                int c16 = 2 * s + ((lane >> 3) & 1);
                ldm_x4(t4, bB + SWZ(row * 128 + c16 * 16));
                bfr[nb2 * 2][0] = t4[0]; bfr[nb2 * 2][1] = t4[1];
                bfr[nb2 * 2 + 1][0] = t4[2]; bfr[nb2 * 2 + 1][1] = t4[3];
            }
#pragma unroll
            for (int mi = 0; mi < 2; mi++)
#pragma unroll
                for (int ni = 0; ni < 8; ni++)
                    mma_bf16(acc[mi][ni], afr[mi], bfr[ni]);
        }
        __syncthreads();                   // buffer reusable
    }

    // ---- epilogue: approx dist + per-(q,tile) top-4 ----
    float* slab  = (float*)(smem + SA_OFF);          // 32 x 128 floats
    float* candd = (float*)(smem + SB_OFF);          // 32 x 32
    int*   candi = (int*)(smem + SB_OFF + 4096);     // 32 x 32

    for (int ms = 0; ms < 4; ms++) {
        __syncthreads();
        if (wm == ms) {
#pragma unroll
            for (int mi = 0; mi < 2; mi++)
#pragma unroll
                for (int ni = 0; ni < 8; ni++)
#pragma unroll
                    for (int c = 0; c < 4; c++) {
                        int row = mi * 16 + (lane >> 2) + (c >> 1) * 8;
                        int col = n_base + ni * 8 + (lane & 3) * 2 + (c & 1);
                        slab[row * 128 + col] = acc[mi][ni][c];
                    }
        }
        __syncthreads();
        // scan: 256 thr = 32 rows x 8 segs x 16 cols
        {
            int r = tid >> 3, seg = tid & 7;
            float t0, t1, t2, t3; int i0, i1, i2, i3;
            t0 = t1 = t2 = t3 = __int_as_float(0x7f800000);
            i0 = i1 = i2 = i3 = 0;
#pragma unroll
            for (int j = 0; j < 16; j++) {
                int col = seg * 16 + j;
                float dh = fmaf(-2.f, slab[r * 128 + col], xsq_s[col]);
                if (dh < t3) {
                    t3 = dh; i3 = n0 + col;
                    if (t3 < t2) { float a = t2; t2 = t3; t3 = a; int bw = i2; i2 = i3; i3 = bw;
                        if (t2 < t1) { a = t1; t1 = t2; t2 = a; bw = i1; i1 = i2; i2 = bw;
                            if (t1 < t0) { a = t0; t0 = t1; t1 = a; bw = i0; i0 = i1; i1 = bw; }
                        }
                    }
                }
            }
            int base = r * 32 + seg * 4;
            candd[base] = t0; candd[base + 1] = t1; candd[base + 2] = t2; candd[base + 3] = t3;
            candi[base] = i0; candi[base + 1] = i1; candi[base + 2] = i2; candi[base + 3] = i3;
        }
        __syncthreads();
        if (tid < 32) {
            float t0, t1, t2, t3; int i0, i1, i2, i3;
            t0 = t1 = t2 = t3 = __int_as_float(0x7f800000);
            i0 = i1 = i2 = i3 = 0x7fffffff;
#pragma unroll
            for (int t = 0; t < 32; t++) {
                float d = candd[tid * 32 + t]; int i = candi[tid * 32 + t];
                if (d < t3 || (d == t3 && i < i3)) {
                    t3 = d; i3 = i;
                    if (t3 < t2 || (t3 == t2 && i3 < i2)) { float a = t2; t2 = t3; t3 = a; int bw = i2; i2 = i3; i3 = bw;
                        if (t2 < t1 || (t2 == t1 && i2 < i1)) { a = t1; t1 = t2; t2 = a; bw = i1; i1 = i2; i2 = bw;
                            if (t1 < t0 || (t1 == t0 && i1 < i0)) { a = t0; t0 = t1; t1 = a; bw = i0; i0 = i1; i1 = bw; }
                        }
                    }
                }
            }
            int q = qh * TM + ms * 32 + tid;
            g_cd4[(size_t)q * NTILES + bx] = make_float4(t0, t1, t2, t3);
            g_ci4[(size_t)q * NTILES + bx] = make_int4(i0, i1, i2, i3);
        }
    }
}

// ---------------- kernel 3: merge approx candidates + exact rescore ----------------
__global__ __launch_bounds__(256)
void merge_kernel(const float* __restrict__ query, const float* __restrict__ lib,
                  float* __restrict__ out) {
    __shared__ float qrow[D];
    __shared__ float sd[1536];
    __shared__ int   si[1536];
    __shared__ float wred[8];
    __shared__ int   wredi[8];
    __shared__ int   sel[KSEL];
    __shared__ float ed[KSEL];
    __shared__ int   eidx[KSEL];
    __shared__ float s_qsq;

    const int q = blockIdx.x, tid = threadIdx.x, lane = tid & 31, w = tid >> 5;
    const float INF = __int_as_float(0x7f800000);

    for (int i = tid; i < D; i += 256) qrow[i] = query[(size_t)q * D + i];
    __syncthreads();
    {
        float s = 0.f;
        for (int i = tid; i < D; i += 256) s = fmaf(qrow[i], qrow[i], s);
#pragma unroll
        for (int o = 16; o; o >>= 1) s += __shfl_xor_sync(0xffffffffu, s, o);
        if (lane == 0) wred[w] = s;
        __syncthreads();
        if (tid == 0) { float t = 0.f; for (int i = 0; i < 8; i++) t += wred[i]; s_qsq = t; }
    }

    const float* cd = (const float*)g_cd4 + (size_t)q * NTILES * 4;
    const int*   ci = (const int*)g_ci4 + (size_t)q * NTILES * 4;
    float d6[6]; int x6[6];
#pragma unroll
    for (int j = 0; j < 6; j++) { d6[j] = INF; x6[j] = 0x7fffffff; }
    for (int j = 0; j < 32; j++) {
        int s2 = tid + j * 256;
        float dv = cd[s2]; int iv = ci[s2];
        if (dv < d6[5]) {
            d6[5] = dv; x6[5] = iv;
#pragma unroll
            for (int p = 5; p > 0; p--)
                if (d6[p] < d6[p - 1]) {
                    float a = d6[p]; d6[p] = d6[p - 1]; d6[p - 1] = a;
                    int bw = x6[p]; x6[p] = x6[p - 1]; x6[p - 1] = bw;
                }
        }
    }
#pragma unroll
    for (int j = 0; j < 6; j++) { sd[tid * 6 + j] = d6[j]; si[tid * 6 + j] = x6[j]; }
    __syncthreads();

    for (int it = 0; it < KSEL; it++) {
        float bd = INF; int bs = -1;
#pragma unroll
        for (int j = 0; j < 6; j++) {
            int s2 = tid * 6 + j;
            float v = sd[s2];
            if (v < bd) { bd = v; bs = s2; }
        }
#pragma unroll
        for (int o = 16; o; o >>= 1) {
            float od = __shfl_down_sync(0xffffffffu, bd, o);
            int   os = __shfl_down_sync(0xffffffffu, bs, o);
            if (od < bd) { bd = od; bs = os; }
        }
        if (lane == 0) { wred[w] = bd; wredi[w] = bs; }
        __syncthreads();
        if (tid == 0) {
            float m = INF; int ms = -1;
            for (int ww = 0; ww < 8; ww++) if (wred[ww] < m) { m = wred[ww]; ms = wredi[ww]; }
            sel[it] = si[ms];
            sd[ms] = INF;
        }
        __syncthreads();
    }

    for (int c = w; c < KSEL; c += 8) {
        int n = sel[c];
        const float* xr = lib + (size_t)n * D;
        float dot = 0.f, ssq = 0.f;
#pragma unroll
        for (int j = 0; j < D / 32; j++) {
            float xv = xr[lane + j * 32], qv = qrow[lane + j * 32];
            dot = fmaf(qv, xv, dot);
            ssq = fmaf(xv, xv, ssq);
        }
#pragma unroll
        for (int o = 16; o; o >>= 1) {
            dot += __shfl_xor_sync(0xffffffffu, dot, o);
            ssq += __shfl_xor_sync(0xffffffffu, ssq, o);
        }
        if (lane == 0) { ed[c] = s_qsq - 2.f * dot + ssq; eidx[c] = n; }
    }
    __syncthreads();

    if (tid == 0) {
        unsigned used = 0;
        for (int it = 0; it < KTOP; it++) {
            float bd = INF; int bi = 0x7fffffff, b = -1;
            for (int c = 0; c < KSEL; c++)
                if (!((used >> c) & 1u)) {
                    if (ed[c] < bd || (ed[c] == bd && eidx[c] < bi)) { bd = ed[c]; bi = eidx[c]; b = c; }
                }
            used |= 1u << b;
            out[q * KTOP + it]               = bd;
            out[QTOT * KTOP + q * KTOP + it] = (float)bi;
        }
    }
}

// ---------------- launcher ----------------
extern "C" void kernel_launch(void* const* d_in, const int* in_sizes, int n_in,
                              void* d_out, int out_size) {
    const float* query = (const float*)d_in[0];
    const float* lib   = (const float*)d_in[1];
    float* out = (float*)d_out;
    (void)n_in; (void)out_size; (void)in_sizes;

    cudaFuncSetAttribute(dist_kernel,
                         cudaFuncAttributeMaxDynamicSharedMemorySize, SMEM_TOTAL);

    qconv_kernel<<<QTOT * D / 8 / 256, 256>>>(query);
    libconv_kernel<<<NTOT / 8, 256>>>(lib);
    dim3 grid(QTOT / TM, NTILES);
    dist_kernel<<<grid, 256, SMEM_TOTAL>>>();
    merge_kernel<<<QTOT, 256>>>(query, lib, out);
}